// round 17
// baseline (speedup 1.0000x reference)
#include <cuda_runtime.h>
#include <math.h>

// ---------------- problem constants ----------------
#define BB       2
#define SEQ      2048
#define DMODEL   1024
#define DCONV    4
#define HEADDIM  64
#define CHUNKL   256
#define DINNER   2048
#define NHEADS   32
#define CONVDIM  2304   // DINNER + 2*DSTATE
#define DINPROJ  4384   // 2*DINNER + 2*DSTATE + NHEADS
#define DSTATE   128
#define DFF      4096
#define NC       8      // SEQ / CHUNKL
#define NROWS    (BB*SEQ)   // 4096

// ---------------- scratch (device globals; no runtime alloc) ----------------
__device__ float g_zx[(size_t)NROWS*DINPROJ];
__device__ float g_xbc[(size_t)NROWS*CONVDIM];
__device__ float g_xdt[(size_t)NROWS*DINNER];
__device__ float g_dt[(size_t)NROWS*NHEADS];
__device__ float g_draw[(size_t)NROWS*NHEADS];
__device__ float g_acum[(size_t)BB*NHEADS*SEQ];
__device__ float g_G[(size_t)BB*NC*CHUNKL*CHUNKL];
__device__ float g_states[(size_t)BB*NC*NHEADS*HEADDIM*DSTATE];
__device__ float g_prev  [(size_t)BB*NC*NHEADS*HEADDIM*DSTATE];
__device__ float g_y[(size_t)NROWS*DINNER];
__device__ float g_hidden[(size_t)NROWS*DMODEL];
__device__ float g_h[(size_t)NROWS*DMODEL];
__device__ float g_ff[(size_t)NROWS*DFF];
__device__ float g_ff2[(size_t)NROWS*DMODEL];

// ---------------- helpers ----------------
__device__ __forceinline__ float softplusf(float x) {
    return (x > 20.f) ? x : log1pf(expf(x));
}
__device__ __forceinline__ float siluf(float x) {
    return x / (1.f + expf(-x));
}
__device__ __forceinline__ float tf32r(float x) {
    unsigned r;
    asm("cvt.rna.tf32.f32 %0, %1;" : "=r"(r) : "f"(x));
    return __uint_as_float(r);
}
__device__ __forceinline__ unsigned tf32u(float x) {
    unsigned r;
    asm("cvt.rna.tf32.f32 %0, %1;" : "=r"(r) : "f"(x));
    return r;
}
__device__ __forceinline__ unsigned smem_u32(const void* p) {
    unsigned a;
    asm("{ .reg .u64 t; cvta.to.shared.u64 t, %1; cvt.u32.u64 %0, t; }" : "=r"(a) : "l"(p));
    return a;
}
__device__ __forceinline__ void mma_tf32(float* c, const unsigned* a, const unsigned* b) {
    asm volatile("mma.sync.aligned.m16n8k8.row.col.f32.tf32.tf32.f32 "
                 "{%0,%1,%2,%3}, {%4,%5,%6,%7}, {%8,%9}, {%0,%1,%2,%3};"
                 : "+f"(c[0]), "+f"(c[1]), "+f"(c[2]), "+f"(c[3])
                 : "r"(a[0]), "r"(a[1]), "r"(a[2]), "r"(a[3]),
                   "r"(b[0]), "r"(b[1]));
}
// block reduction over 256 threads (8 warps) via shuffles, 1 barrier
__device__ __forceinline__ float block_sum256(float v, float* red8, int tid) {
#pragma unroll
    for (int o = 16; o > 0; o >>= 1)
        v += __shfl_down_sync(0xffffffffu, v, o);
    if ((tid & 31) == 0) red8[tid >> 5] = v;
    __syncthreads();
    float s = (tid < 8) ? red8[tid] : 0.f;
#pragma unroll
    for (int o = 4; o > 0; o >>= 1)
        s += __shfl_down_sync(0xffu, s, o);
    return __shfl_sync(0xffffffffu, s, 0, 32);   // valid in warp 0
}

// ---------------- cp.async pipelined TF32 GEMM: C = act(A@B+bias) -----------
// CTA tile 128x128, warp tile 32x64, 3-stage pipeline, 2 CTAs/SM.  (champion)
#define GSTAGES 3
#define ASTR    20                       // A smem stride (floats): conflict-free
#define BSTR    136                      // B smem stride (floats)
#define A_STF   (128*ASTR)               // 2560 floats per A stage
#define B_STF   (16*BSTR)                // 2176 floats per B stage
#define ST_F    (A_STF + B_STF)          // 4736
#define GT_SMEM (GSTAGES*ST_F*4)         // 56832 bytes

#define GT_ISSUE(stg, kt) do {                                                      \
    unsigned sb = smb + (unsigned)(stg) * (ST_F * 4);                               \
    unsigned bbs = sb + A_STF * 4;                                                  \
    int k0i = (kt) * 16;                                                            \
    _Pragma("unroll")                                                               \
    for (int u = 0; u < 2; u++) {                                                   \
        int c = tid * 2 + u;                                                        \
        int m = c >> 2, kq = (c & 3) << 2;                                          \
        const float* sp = A + (size_t)(row0 + m) * K + k0i + kq;                    \
        asm volatile("cp.async.cg.shared.global [%0], [%1], 16;"                    \
                     :: "r"(sb + (unsigned)(m * ASTR + kq) * 4), "l"(sp));          \
        int kk = c >> 5, nq = (c & 31) << 2;                                        \
        int gc = col0 + nq;                                                         \
        const float* sp2 = (gc < N) ? (B + (size_t)(k0i + kk) * N + gc) : B;        \
        int by = (gc < N) ? 16 : 0;                                                 \
        asm volatile("cp.async.cg.shared.global [%0], [%1], 16, %2;"                \
                     :: "r"(bbs + (unsigned)(kk * BSTR + nq) * 4), "l"(sp2), "r"(by)); \
    }                                                                               \
    asm volatile("cp.async.commit_group;" ::: "memory");                            \
} while (0)

__global__ __launch_bounds__(256, 2)
void gemm_tc(const float* __restrict__ A, const float* __restrict__ B,
             const float* __restrict__ bias, float* __restrict__ C,
             int M, int N, int K, int act)
{
    extern __shared__ float sm[];
    unsigned smb = smem_u32(sm);
    int tid = threadIdx.x;
    int lane = tid & 31, wid = tid >> 5;
    int wm = (wid >> 1) * 32;
    int wn = (wid & 1) * 64;
    int g = lane >> 2, tig = lane & 3;
    int row0 = blockIdx.y * 128, col0 = blockIdx.x * 128;

    float acc[2][8][4];
#pragma unroll
    for (int i = 0; i < 2; i++)
#pragma unroll
        for (int j = 0; j < 8; j++)
#pragma unroll
            for (int v = 0; v < 4; v++) acc[i][j][v] = 0.f;

    int nt = K / 16;           // >= 64 for all call sites
    GT_ISSUE(0, 0);
    GT_ISSUE(1, 1);

    int stg = 0;               // buffer holding tile t
    for (int t = 0; t < nt; t++) {
        if (t + 2 <= nt) asm volatile("cp.async.wait_group 1;" ::: "memory");
        else             asm volatile("cp.async.wait_group 0;" ::: "memory");
        __syncthreads();
        if (t + 2 < nt) {
            int nstg = stg + 2; if (nstg >= GSTAGES) nstg -= GSTAGES;
            GT_ISSUE(nstg, t + 2);
        }

        const float* Ab = sm + stg * ST_F;
        const float* Bb = Ab + A_STF;
#pragma unroll
        for (int ks = 0; ks < 2; ks++) {
            int kb = ks * 8;
            unsigned af[2][4], bf[8][2];
#pragma unroll
            for (int mt = 0; mt < 2; mt++) {
                int m = wm + mt * 16;
                af[mt][0] = tf32u(Ab[(m + g) * ASTR + kb + tig]);
                af[mt][1] = tf32u(Ab[(m + g + 8) * ASTR + kb + tig]);
                af[mt][2] = tf32u(Ab[(m + g) * ASTR + kb + tig + 4]);
                af[mt][3] = tf32u(Ab[(m + g + 8) * ASTR + kb + tig + 4]);
            }
#pragma unroll
            for (int nt2 = 0; nt2 < 8; nt2++) {
                int n = wn + nt2 * 8;
                bf[nt2][0] = tf32u(Bb[(kb + tig) * BSTR + n + g]);
                bf[nt2][1] = tf32u(Bb[(kb + tig + 4) * BSTR + n + g]);
            }
#pragma unroll
            for (int mt = 0; mt < 2; mt++)
#pragma unroll
                for (int nt2 = 0; nt2 < 8; nt2++)
                    mma_tf32(acc[mt][nt2], af[mt], bf[nt2]);
        }
        stg++; if (stg >= GSTAGES) stg = 0;
    }

    // epilogue
#pragma unroll
    for (int mt = 0; mt < 2; mt++) {
        int r = row0 + wm + mt * 16 + g;
#pragma unroll
        for (int nt2 = 0; nt2 < 8; nt2++) {
            int col = col0 + wn + nt2 * 8 + 2 * tig;
            if (col < N) {
                float b0 = bias[col], b1 = bias[col + 1];
                float v0 = acc[mt][nt2][0] + b0;
                float v1 = acc[mt][nt2][1] + b1;
                float v2 = acc[mt][nt2][2] + b0;
                float v3 = acc[mt][nt2][3] + b1;
                if (act == 1) {
                    float t;
                    t = fminf(fmaxf(v0 + 3.f, 0.f), 6.f); v0 = v0 * t * (1.f / 6.f);
                    t = fminf(fmaxf(v1 + 3.f, 0.f), 6.f); v1 = v1 * t * (1.f / 6.f);
                    t = fminf(fmaxf(v2 + 3.f, 0.f), 6.f); v2 = v2 * t * (1.f / 6.f);
                    t = fminf(fmaxf(v3 + 3.f, 0.f), 6.f); v3 = v3 * t * (1.f / 6.f);
                }
                C[(size_t)r * N + col] = v0;
                C[(size_t)r * N + col + 1] = v1;
                C[(size_t)(r + 8) * N + col] = v2;
                C[(size_t)(r + 8) * N + col + 1] = v3;
            }
        }
    }
}

// ---------------- exact fp32 dt_raw ----------------
__global__ void dtraw_kernel(const float* __restrict__ x, const float* __restrict__ W_in,
                             const float* __restrict__ b_in)
{
    int row0 = blockIdx.x * 8;
    int tid = threadIdx.x;
    int r = tid >> 5, h = tid & 31;
    __shared__ float xs[8][DMODEL];
    for (int i = tid; i < 8 * DMODEL; i += 256)
        xs[i >> 10][i & 1023] = x[(size_t)(row0 + (i >> 10)) * DMODEL + (i & 1023)];
    __syncthreads();
    const float* wc = W_in + (DINPROJ - NHEADS) + h;
    float a0 = 0.f, a1 = 0.f, a2 = 0.f, a3 = 0.f;
#pragma unroll 2
    for (int k = 0; k < DMODEL; k += 4) {
        a0 = fmaf(xs[r][k + 0], wc[(size_t)(k + 0) * DINPROJ], a0);
        a1 = fmaf(xs[r][k + 1], wc[(size_t)(k + 1) * DINPROJ], a1);
        a2 = fmaf(xs[r][k + 2], wc[(size_t)(k + 2) * DINPROJ], a2);
        a3 = fmaf(xs[r][k + 3], wc[(size_t)(k + 3) * DINPROJ], a3);
    }
    g_draw[(size_t)(row0 + r) * NHEADS + h] =
        b_in[DINPROJ - NHEADS + h] + ((a0 + a1) + (a2 + a3));
}

// ---------------- conv + silu + fused xdt (4 rows x 4 channels / thread) ----
__global__ void conv_kernel(const float* __restrict__ conv_w, const float* __restrict__ conv_b)
{
    int idx = blockIdx.x * blockDim.x + threadIdx.x;
    if (idx >= (NROWS / 4) * (CONVDIM / 4)) return;
    int ch4 = (idx % (CONVDIM / 4)) * 4;
    int rg = idx / (CONVDIM / 4);
    int row0 = rg * 4;
    int l0 = row0 % SEQ;

    float4 w0 = *(const float4*)(conv_w + (ch4 + 0) * DCONV);
    float4 w1 = *(const float4*)(conv_w + (ch4 + 1) * DCONV);
    float4 w2 = *(const float4*)(conv_w + (ch4 + 2) * DCONV);
    float4 w3 = *(const float4*)(conv_w + (ch4 + 3) * DCONV);
    float4 bv = *(const float4*)(conv_b + ch4);

    float4 v[7];
#pragma unroll
    for (int j = 0; j < 7; j++) {
        int l = l0 + j - 3;
        if (l >= 0)
            v[j] = *(const float4*)(g_zx + (size_t)(row0 + j - 3) * DINPROJ + DINNER + ch4);
        else
            v[j] = make_float4(0.f, 0.f, 0.f, 0.f);
    }

    int head = ch4 >> 6;
    bool isx = ch4 < DINNER;
#pragma unroll
    for (int i = 0; i < 4; i++) {
        float4 a;
        a.x = bv.x + v[i].x * w0.x + v[i + 1].x * w0.y + v[i + 2].x * w0.z + v[i + 3].x * w0.w;
        a.y = bv.y + v[i].y * w1.x + v[i + 1].y * w1.y + v[i + 2].y * w1.z + v[i + 3].y * w1.w;
        a.z = bv.z + v[i].z * w2.x + v[i + 1].z * w2.y + v[i + 2].z * w2.z + v[i + 3].z * w2.w;
        a.w = bv.w + v[i].w * w3.x + v[i + 1].w * w3.y + v[i + 2].w * w3.z + v[i + 3].w * w3.w;
        float4 o;
        o.x = siluf(a.x); o.y = siluf(a.y); o.z = siluf(a.z); o.w = siluf(a.w);
        size_t row = row0 + i;
        *(float4*)(g_xbc + row * CONVDIM + ch4) = o;
        if (isx) {
            float dt = g_dt[row * NHEADS + head];
            float4 xo;
            xo.x = o.x * dt; xo.y = o.y * dt; xo.z = o.z * dt; xo.w = o.w * dt;
            *(float4*)(g_xdt + row * DINNER + ch4) = xo;
        }
    }
}

// ---------------- dt / dA + per-chunk inclusive cumsum (shuffle scan) -------
__global__ void dtscan_kernel(const float* __restrict__ tdiff,
                              const float* __restrict__ A_log,
                              const float* __restrict__ dt_bias,
                              const float* __restrict__ time_decay)
{
    int blk = blockIdx.x;
    int c = blk % NC;
    int h = (blk / NC) % NHEADS;
    int b = blk / (NC * NHEADS);
    int l = threadIdx.x;
    int lane = l & 31, wid = l >> 5;
    __shared__ float wsum[8];
    int row = b * SEQ + c * CHUNKL + l;
    float draw = g_draw[(size_t)row * NHEADS + h];
    float dt = softplusf(draw + dt_bias[h]);
    float Ah = -expf(A_log[h]);
    float spd = softplusf(time_decay[h]);
    float val = dt * Ah - spd * tdiff[row];
    g_dt[(size_t)row * NHEADS + h] = dt;
#pragma unroll
    for (int o = 1; o < 32; o <<= 1) {
        float n = __shfl_up_sync(0xffffffffu, val, o);
        if (lane >= o) val += n;
    }
    if (lane == 31) wsum[wid] = val;
    __syncthreads();
    if (wid == 0 && lane < 8) {
        float w = wsum[lane];
#pragma unroll
        for (int o = 1; o < 8; o <<= 1) {
            float n = __shfl_up_sync(0xffu, w, o);
            if (lane >= o) w += n;
        }
        wsum[lane] = w;
    }
    __syncthreads();
    if (wid > 0) val += wsum[wid - 1];
    g_acum[((size_t)(b * NHEADS + h)) * SEQ + c * CHUNKL + l] = val;
}

// ---------------- G = C @ B^T per (b,chunk)  [tf32 mma, 64x64 tiles] --------
__global__ __launch_bounds__(256)
void cbgemm_kernel()
{
    int bc = blockIdx.z;
    int l0 = blockIdx.y * 64, s0 = blockIdx.x * 64;
    __shared__ float As[16][72];
    __shared__ float Bs2[16][72];
    int tid = threadIdx.x;
    int lane = tid & 31, wid = tid >> 5;
    int wm = (wid & 3) * 16;
    int wn = (wid >> 2) * 32;
    int g = lane >> 2, tig = lane & 3;

    float acc[4][4];
#pragma unroll
    for (int j = 0; j < 4; j++)
#pragma unroll
        for (int v = 0; v < 4; v++) acc[j][v] = 0.f;

    const float* base = g_xbc + (size_t)bc * CHUNKL * CONVDIM;
    int r = tid >> 2, c4 = (tid & 3) << 2;
    for (int n0 = 0; n0 < DSTATE; n0 += 16) {
        float4 vc = *(const float4*)(base + (size_t)(l0 + r) * CONVDIM + DINNER + DSTATE + n0 + c4);
        As[c4 + 0][r] = tf32r(vc.x); As[c4 + 1][r] = tf32r(vc.y);
        As[c4 + 2][r] = tf32r(vc.z); As[c4 + 3][r] = tf32r(vc.w);
        float4 vb = *(const float4*)(base + (size_t)(s0 + r) * CONVDIM + DINNER + n0 + c4);
        Bs2[c4 + 0][r] = tf32r(vb.x); Bs2[c4 + 1][r] = tf32r(vb.y);
        Bs2[c4 + 2][r] = tf32r(vb.z); Bs2[c4 + 3][r] = tf32r(vb.w);
        __syncthreads();
#pragma unroll
        for (int ks = 0; ks < 2; ks++) {
            int kb = ks * 8;
            unsigned af[4], bf[4][2];
            af[0] = __float_as_uint(As[kb + tig][wm + g]);
            af[1] = __float_as_uint(As[kb + tig][wm + g + 8]);
            af[2] = __float_as_uint(As[kb + tig + 4][wm + g]);
            af[3] = __float_as_uint(As[kb + tig + 4][wm + g + 8]);
#pragma unroll
            for (int nt = 0; nt < 4; nt++) {
                int n = wn + nt * 8;
                bf[nt][0] = __float_as_uint(Bs2[kb + tig][n + g]);
                bf[nt][1] = __float_as_uint(Bs2[kb + tig + 4][n + g]);
            }
#pragma unroll
            for (int nt = 0; nt < 4; nt++)
                mma_tf32(acc[nt], af, bf[nt]);
        }
        __syncthreads();
    }
    float* Gp = g_G + (size_t)bc * CHUNKL * CHUNKL;
    int rr = l0 + wm + g;
#pragma unroll
    for (int nt = 0; nt < 4; nt++) {
        int col = s0 + wn + nt * 8 + 2 * tig;
        Gp[(size_t)rr * CHUNKL + col]     = acc[nt][0];
        Gp[(size_t)rr * CHUNKL + col + 1] = acc[nt][1];
        Gp[(size_t)(rr + 8) * CHUNKL + col]     = acc[nt][2];
        Gp[(size_t)(rr + 8) * CHUNKL + col + 1] = acc[nt][3];
    }
}

// ---------------- chunk states  [tf32 mma, __expf, double-buffered] ---------
__global__ __launch_bounds__(256)
void states_kernel()
{
    int bch = blockIdx.x;
    int h = bch % NHEADS;
    int bc = bch / NHEADS;
    int b = bc / NC, c = bc % NC;
    int tid = threadIdx.x;
    int lane = tid & 31, wid = tid >> 5;
    int wm = (wid >> 1) * 16;
    int wn = (wid & 1) * 64;
    int g = lane >> 2, tig = lane & 3;

    __shared__ float w[CHUNKL];
    __shared__ float As[2][16][72];
    __shared__ float Bs[2][16][136];
    const float* ac = g_acum + ((size_t)(b * NHEADS + h)) * SEQ + c * CHUNKL;
    w[tid] = __expf(ac[CHUNKL - 1] - ac[tid]);
    __syncthreads();

    float acc[8][4];
#pragma unroll
    for (int j = 0; j < 8; j++)
#pragma unroll
        for (int v = 0; v < 4; v++) acc[j][v] = 0.f;

    int lr = tid >> 4, pc = (tid & 15) << 2;
    int lr2a = (tid * 2) >> 5, nc4a = ((tid * 2) & 31) << 2;
    int lr2b = (tid * 2 + 1) >> 5, nc4b = ((tid * 2 + 1) & 31) << 2;

    // prologue: build buffer 0
    {
        float4 v = *(const float4*)(g_xdt + ((size_t)(bc * CHUNKL + lr)) * DINNER + h * HEADDIM + pc);
        float ww = w[lr];
        As[0][lr][pc + 0] = tf32r(v.x * ww); As[0][lr][pc + 1] = tf32r(v.y * ww);
        As[0][lr][pc + 2] = tf32r(v.z * ww); As[0][lr][pc + 3] = tf32r(v.w * ww);
        float4 vb0 = *(const float4*)(g_xbc + ((size_t)(bc * CHUNKL + lr2a)) * CONVDIM + DINNER + nc4a);
        Bs[0][lr2a][nc4a + 0] = tf32r(vb0.x); Bs[0][lr2a][nc4a + 1] = tf32r(vb0.y);
        Bs[0][lr2a][nc4a + 2] = tf32r(vb0.z); Bs[0][lr2a][nc4a + 3] = tf32r(vb0.w);
        float4 vb1 = *(const float4*)(g_xbc + ((size_t)(bc * CHUNKL + lr2b)) * CONVDIM + DINNER + nc4b);
        Bs[0][lr2b][nc4b + 0] = tf32r(vb1.x); Bs[0][lr2b][nc4b + 1] = tf32r(vb1.y);
        Bs[0][lr2b][nc4b + 2] = tf32r(vb1.z); Bs[0][lr2b][nc4b + 3] = tf32r(vb1.w);
    }
    __syncthreads();

    for (int it = 0; it < 16; it++) {
        int cur = it & 1;
        float4 v, vb0, vb1;
        float ww = 0.f;
        bool more = (it + 1 < 16);
        if (more) {
            int l0 = (it + 1) * 16;
            v = *(const float4*)(g_xdt + ((size_t)(bc * CHUNKL + l0 + lr)) * DINNER + h * HEADDIM + pc);
            ww = w[l0 + lr];
            vb0 = *(const float4*)(g_xbc + ((size_t)(bc * CHUNKL + l0 + lr2a)) * CONVDIM + DINNER + nc4a);
            vb1 = *(const float4*)(g_xbc + ((size_t)(bc * CHUNKL + l0 + lr2b)) * CONVDIM + DINNER + nc4b);
        }
        // compute from current buffer
#pragma unroll
        for (int ks = 0; ks < 2; ks++) {
            int kb = ks * 8;
            unsigned af[4], bf[8][2];
            af[0] = __float_as_uint(As[cur][kb + tig][wm + g]);
            af[1] = __float_as_uint(As[cur][kb + tig][wm + g + 8]);
            af[2] = __float_as_uint(As[cur][kb + tig + 4][wm + g]);
            af[3] = __float_as_uint(As[cur][kb + tig + 4][wm + g + 8]);
#pragma unroll
            for (int nt = 0; nt < 8; nt++) {
                int n = wn + nt * 8;
                bf[nt][0] = __float_as_uint(Bs[cur][kb + tig][n + g]);
                bf[nt][1] = __float_as_uint(Bs[cur][kb + tig + 4][n + g]);
            }
#pragma unroll
            for (int nt = 0; nt < 8; nt++)
                mma_tf32(acc[nt], af, bf[nt]);
        }
        if (more) {
            int nx = cur ^ 1;
            As[nx][lr][pc + 0] = tf32r(v.x * ww); As[nx][lr][pc + 1] = tf32r(v.y * ww);
            As[nx][lr][pc + 2] = tf32r(v.z * ww); As[nx][lr][pc + 3] = tf32r(v.w * ww);
            Bs[nx][lr2a][nc4a + 0] = tf32r(vb0.x); Bs[nx][lr2a][nc4a + 1] = tf32r(vb0.y);
            Bs[nx][lr2a][nc4a + 2] = tf32r(vb0.z); Bs[nx][lr2a][nc4a + 3] = tf32r(vb0.w);
            Bs[nx][lr2b][nc4b + 0] = tf32r(vb1.x); Bs[nx][lr2b][nc4b + 1] = tf32r(vb1.y);
            Bs[nx][lr2b][nc4b + 2] = tf32r(vb1.z); Bs[nx][lr2b][nc4b + 3] = tf32r(vb1.w);
        }
        __syncthreads();
    }
    float* sp = g_states + (size_t)bch * HEADDIM * DSTATE;
    int r = wm + g;
#pragma unroll
    for (int nt = 0; nt < 8; nt++) {
        int col = wn + nt * 8 + 2 * tig;
        sp[(size_t)r * DSTATE + col]     = acc[nt][0];
        sp[(size_t)r * DSTATE + col + 1] = acc[nt][1];
        sp[(size_t)(r + 8) * DSTATE + col]     = acc[nt][2];
        sp[(size_t)(r + 8) * DSTATE + col + 1] = acc[nt][3];
    }
}

// ---------------- inter-chunk scan  [__expf] ----------------
__global__ void scan_kernel()
{
    int idx = blockIdx.x * blockDim.x + threadIdx.x;
    if (idx >= BB * NHEADS * HEADDIM * DSTATE) return;
    int n = idx & 127;
    int p = (idx >> 7) & 63;
    int h = (idx >> 13) & 31;
    int b = idx >> 18;
    float carry = 0.f;
    for (int c = 0; c < NC; c++) {
        size_t off = ((size_t)((b * NC + c) * NHEADS + h)) * (HEADDIM * DSTATE) + p * DSTATE + n;
        g_prev[off] = carry;
        float cd = __expf(g_acum[((size_t)(b * NHEADS + h)) * SEQ + c * CHUNKL + CHUNKL - 1]);
        carry = carry * cd + g_states[off];
    }
}

// ---------------- Y = (Y_diag + Y_off + D*xh) * silu(z)  [double-buffered] --
__global__ __launch_bounds__(256)
void ydiag_kernel(const float* __restrict__ Dp)
{
    int bch = blockIdx.x;
    int h = bch % NHEADS;
    int bc = bch / NHEADS;
    int b = bc / NC;
    int tid = threadIdx.x;
    int lane = tid & 31, wid = tid >> 5;
    int g = lane >> 2, tig = lane & 3;
    int wm = wid * 32;

    __shared__ float Acs[CHUNKL];
    __shared__ float Gs[2][16][260];
    __shared__ float Xs[2][16][68];

    const float* ac = g_acum + ((size_t)(b * NHEADS + h)) * SEQ + (bc % NC) * CHUNKL;
    Acs[tid] = ac[tid];
    __syncthreads();
    float al = Acs[tid];
    float eal = __expf(al);

    float acc[2][8][4];
#pragma unroll
    for (int i = 0; i < 2; i++)
#pragma unroll
        for (int j = 0; j < 8; j++)
#pragma unroll
            for (int v = 0; v < 4; v++) acc[i][j][v] = 0.f;

    const float* Gp = g_G + (size_t)bc * CHUNKL * CHUNKL;
    int lr = tid >> 4, pc = (tid & 15) << 2;

    // ---- phase 1: Y_diag ----
    // prologue: build buffer 0 (s0 = 0)
    {
        float4 gv[4];
#pragma unroll
        for (int q = 0; q < 4; q++)
            gv[q] = *(const float4*)(Gp + (size_t)tid * CHUNKL + q * 4);
        const float* gf = (const float*)gv;
#pragma unroll
        for (int i = 0; i < 16; i++) {
            float v = 0.f;
            if (tid >= i) v = gf[i] * __expf(al - Acs[i]);
            Gs[0][i][tid] = tf32r(v);
        }
        float4 v4 = *(const float4*)(g_xdt + ((size_t)(bc * CHUNKL + lr)) * DINNER + h * HEADDIM + pc);
        Xs[0][lr][pc + 0] = tf32r(v4.x); Xs[0][lr][pc + 1] = tf32r(v4.y);
        Xs[0][lr][pc + 2] = tf32r(v4.z); Xs[0][lr][pc + 3] = tf32r(v4.w);
    }
    __syncthreads();

    for (int it = 0; it < 16; it++) {
        int cur = it & 1;
        bool more = (it + 1 < 16);
        float4 gv[4], v4;
        if (more) {
            int s0 = (it + 1) * 16;
#pragma unroll
            for (int q = 0; q < 4; q++)
                gv[q] = *(const float4*)(Gp + (size_t)tid * CHUNKL + s0 + q * 4);
            v4 = *(const float4*)(g_xdt + ((size_t)(bc * CHUNKL + s0 + lr)) * DINNER + h * HEADDIM + pc);
        }
        // compute from current buffer
#pragma unroll
        for (int ks = 0; ks < 2; ks++) {
            int kb = ks * 8;
            unsigned af[2][4], bf[8][2];
#pragma unroll
            for (int mt = 0; mt < 2; mt++) {
                int m = wm + mt * 16;
                af[mt][0] = __float_as_uint(Gs[cur][kb + tig][m + g]);
                af[mt][1] = __float_as_uint(Gs[cur][kb + tig][m + g + 8]);
                af[mt][2] = __float_as_uint(Gs[cur][kb + tig + 4][m + g]);
                af[mt][3] = __float_as_uint(Gs[cur][kb + tig + 4][m + g + 8]);
            }
#pragma unroll
            for (int nt = 0; nt < 8; nt++) {
                int n = nt * 8;
                bf[nt][0] = __float_as_uint(Xs[cur][kb + tig][n + g]);
                bf[nt][1] = __float_as_uint(Xs[cur][kb + tig + 4][n + g]);
            }
#pragma unroll
            for (int mt = 0; mt < 2; mt++)
#pragma unroll
                for (int nt = 0; nt < 8; nt++)
                    mma_tf32(acc[mt][nt], af[mt], bf[nt]);
        }
        if (more) {
            int s0 = (it + 1) * 16;
            int nx = cur ^ 1;
            const float* gf = (const float*)gv;
#pragma unroll
            for (int i = 0; i < 16; i++) {
                int s = s0 + i;
                float v = 0.f;
                if (tid >= s) v = gf[i] * __expf(al - Acs[s]);
                Gs[nx][i][tid] = tf32r(v);
            }
            Xs[nx][lr][pc + 0] = tf32r(v4.x); Xs[nx][lr][pc + 1] = tf32r(v4.y);
            Xs[nx][lr][pc + 2] = tf32r(v4.z); Xs[nx][lr][pc + 3] = tf32r(v4.w);
        }
        __syncthreads();
    }

    // ---- phase 2: Y_off ----
    const float* pv_base = g_prev + (size_t)bch * HEADDIM * DSTATE;
    int pp = tid >> 2, k4 = (tid & 3) << 2;
    // prologue: build buffer 0 (n0 = 0)
    {
        float4 cv[4];
#pragma unroll
        for (int q = 0; q < 4; q++)
            cv[q] = *(const float4*)(g_xbc + ((size_t)(bc * CHUNKL + tid)) * CONVDIM + DINNER + DSTATE + q * 4);
        const float* cf = (const float*)cv;
#pragma unroll
        for (int i = 0; i < 16; i++)
            Gs[0][i][tid] = tf32r(cf[i] * eal);
        float4 pvv = *(const float4*)(pv_base + (size_t)pp * DSTATE + k4);
        Xs[0][k4 + 0][pp] = tf32r(pvv.x); Xs[0][k4 + 1][pp] = tf32r(pvv.y);
        Xs[0][k4 + 2][pp] = tf32r(pvv.z); Xs[0][k4 + 3][pp] = tf32r(pvv.w);
    }
    __syncthreads();

    for (int it = 0; it < 8; it++) {
        int cur = it & 1;
        bool more = (it + 1 < 8);
        float4 cv[4], pvv;
        if (more) {
            int n0 = (it + 1) * 16;
#pragma unroll
            for (int q = 0; q < 4; q++)
                cv[q] = *(const float4*)(g_xbc + ((size_t)(bc * CHUNKL + tid)) * CONVDIM + DINNER + DSTATE + n0 + q * 4);
            pvv = *(const float4*)(pv_base + (size_t)pp * DSTATE + n0 + k4);
        }
#pragma unroll
        for (int ks = 0; ks < 2; ks++) {
            int kb = ks * 8;
            unsigned af[2][4], bf[8][2];
#pragma unroll
            for (int mt = 0; mt < 2; mt++) {
                int m = wm + mt * 16;
                af[mt][0] = __float_as_uint(Gs[cur][kb + tig][m + g]);
                af[mt][1] = __float_as_uint(Gs[cur][kb + tig][m + g + 8]);
                af[mt][2] = __float_as_uint(Gs[cur][kb + tig + 4][m + g]);
                af[mt][3] = __float_as_uint(Gs[cur][kb + tig + 4][m + g + 8]);
            }
#pragma unroll
            for (int nt = 0; nt < 8; nt++) {
                int n = nt * 8;
                bf[nt][0] = __float_as_uint(Xs[cur][kb + tig][n + g]);
                bf[nt][1] = __float_as_uint(Xs[cur][kb + tig + 4][n + g]);
            }
#pragma unroll
            for (int mt = 0; mt < 2; mt++)
#pragma unroll
                for (int nt = 0; nt < 8; nt++)
                    mma_tf32(acc[mt][nt], af[mt], bf[nt]);
        }
        if (more) {
            int nx = cur ^ 1;
            const float* cf = (const float*)cv;
#pragma unroll
            for (int i = 0; i < 16; i++)
                Gs[nx][i][tid] = tf32r(cf[i] * eal);
            Xs[nx][k4 + 0][pp] = tf32r(pvv.x); Xs[nx][k4 + 1][pp] = tf32r(pvv.y);
            Xs[nx][k4 + 2][pp] = tf32r(pvv.z); Xs[nx][k4 + 3][pp] = tf32r(pvv.w);
        }
        __syncthreads();
    }

    float Dh = Dp[h];
#pragma unroll
    for (int mt = 0; mt < 2; mt++) {
        int r0 = wm + mt * 16 + g;
#pragma unroll
        for (int nt = 0; nt < 8; nt++) {
            int pcol = nt * 8 + 2 * tig;
            int d = h * HEADDIM + pcol;
#pragma unroll
            for (int half = 0; half < 2; half++) {
                int l = r0 + half * 8;
                size_t row = (size_t)bc * CHUNKL + l;
                float xh0 = g_xbc[row * CONVDIM + d];
                float xh1 = g_xbc[row * CONVDIM + d + 1];
                float z0 = g_zx[row * DINPROJ + d];
                float z1 = g_zx[row * DINPROJ + d + 1];
                float v0 = acc[mt][nt][half * 2 + 0] + Dh * xh0;
                float v1 = acc[mt][nt][half * 2 + 1] + Dh * xh1;
                v0 *= siluf(z0);
                v1 *= siluf(z1);
                g_y[row * DINNER + d] = v0;
                g_y[row * DINNER + d + 1] = v1;
            }
        }
    }
}

// ---------------- gated RMS norm (float4 + shuffle reduction) ----------------
__global__ void rms_kernel(const float* __restrict__ rms_w)
{
    int row = blockIdx.x;
    int tid = threadIdx.x;
    float4* y4 = (float4*)(g_y + (size_t)row * DINNER);
    const float4* w4 = (const float4*)rms_w;
    __shared__ float red8[8];
    float4 v0 = y4[tid], v1 = y4[tid + 256];
    float ss = v0.x * v0.x + v0.y * v0.y + v0.z * v0.z + v0.w * v0.w
             + v1.x * v1.x + v1.y * v1.y + v1.z * v1.z + v1.w * v1.w;
    float tot = block_sum256(ss, red8, tid);
    __shared__ float sc;
    if (tid == 0) sc = rsqrtf(tot * (1.f / DINNER) + 1e-12f);
    __syncthreads();
    float scale = sc;
    float4 g0 = w4[tid], g1 = w4[tid + 256];
    v0.x *= scale * g0.x; v0.y *= scale * g0.y; v0.z *= scale * g0.z; v0.w *= scale * g0.w;
    v1.x *= scale * g1.x; v1.y *= scale * g1.y; v1.z *= scale * g1.z; v1.w *= scale * g1.w;
    y4[tid] = v0; y4[tid + 256] = v1;
}

// ---------------- residual add + LayerNorm (float4 + shuffle reduction) ------
__global__ void addln_kernel(const float* __restrict__ in1, const float* __restrict__ res,
                             const float* __restrict__ g, const float* __restrict__ bta,
                             float* __restrict__ out)
{
    int row = blockIdx.x;
    int tid = threadIdx.x;
    __shared__ float red8[8];
    __shared__ float s_mu, s_inv;
    float4 a = ((const float4*)(in1 + (size_t)row * DMODEL))[tid];
    float4 b = ((const float4*)(res + (size_t)row * DMODEL))[tid];
    float4 v;
    v.x = a.x + b.x; v.y = a.y + b.y; v.z = a.z + b.z; v.w = a.w + b.w;
    float s = (v.x + v.y) + (v.z + v.w);
    float tot = block_sum256(s, red8, tid);
    if (tid == 0) s_mu = tot * (1.f / DMODEL);
    __syncthreads();
    float mu = s_mu;
    float dx = v.x - mu, dy = v.y - mu, dz = v.z - mu, dw = v.w - mu;
    float vs = dx * dx + dy * dy + dz * dz + dw * dw;
    float vtot = block_sum256(vs, red8, tid);
    if (tid == 0) s_inv = rsqrtf(vtot * (1.f / DMODEL) + 1e-12f);
    __syncthreads();
    float inv = s_inv;
    float4 gg = ((const float4*)g)[tid];
    float4 bb = ((const float4*)bta)[tid];
    float4 o;
    o.x = dx * inv * gg.x + bb.x;
    o.y = dy * inv * gg.y + bb.y;
    o.z = dz * inv * gg.z + bb.z;
    o.w = dw * inv * gg.w + bb.w;
    ((float4*)(out + (size_t)row * DMODEL))[tid] = o;
}

// ---------------- launch ----------------
extern "C" void kernel_launch(void* const* d_in, const int* in_sizes, int n_in,
                              void* d_out, int out_size)
{
    const float* x          = (const float*)d_in[0];
    const float* time_diff  = (const float*)d_in[1];
    const float* W_in       = (const float*)d_in[2];
    const float* b_in       = (const float*)d_in[3];
    const float* conv_w     = (const float*)d_in[4];
    const float* conv_b     = (const float*)d_in[5];
    const float* A_log      = (const float*)d_in[6];
    const float* dt_bias    = (const float*)d_in[7];
    const float* Dp         = (const float*)d_in[8];
    const float* time_decay = (const float*)d_in[9];
    const float* rms_w      = (const float*)d_in[10];
    const float* W_out      = (const float*)d_in[11];
    const float* b_out      = (const float*)d_in[12];
    const float* ln_g       = (const float*)d_in[13];
    const float* ln_b       = (const float*)d_in[14];
    const float* fc1_w      = (const float*)d_in[15];
    const float* fc1_b      = (const float*)d_in[16];
    const float* fc2_w      = (const float*)d_in[17];
    const float* fc2_b      = (const float*)d_in[18];
    const float* ln2_g      = (const float*)d_in[19];
    const float* ln2_b      = (const float*)d_in[20];
    float* out = (float*)d_out;

    float *p_zx, *p_y, *p_hidden, *p_h, *p_ff, *p_ff2;
    cudaGetSymbolAddress((void**)&p_zx, g_zx);
    cudaGetSymbolAddress((void**)&p_y, g_y);
    cudaGetSymbolAddress((void**)&p_hidden, g_hidden);
    cudaGetSymbolAddress((void**)&p_h, g_h);
    cudaGetSymbolAddress((void**)&p_ff, g_ff);
    cudaGetSymbolAddress((void**)&p_ff2, g_ff2);

    cudaFuncSetAttribute(gemm_tc, cudaFuncAttributeMaxDynamicSharedMemorySize, GT_SMEM);

    // 1. in_proj
    gemm_tc<<<dim3((DINPROJ + 127) / 128, NROWS / 128), 256, GT_SMEM>>>(
        x, W_in, b_in, p_zx, NROWS, DINPROJ, DMODEL, 0);
    // 1b. exact fp32 dt_raw
    dtraw_kernel<<<NROWS / 8, 256>>>(x, W_in, b_in);
    // 2. dt / dA / chunk cumsum (shuffle scan)
    dtscan_kernel<<<BB * NHEADS * NC, CHUNKL>>>(time_diff, A_log, dt_bias, time_decay);
    // 3. conv + silu + fused xdt (4x4 vectorized)
    conv_kernel<<<((NROWS / 4) * (CONVDIM / 4) + 255) / 256, 256>>>(conv_w, conv_b);
    // 4. G = C @ B^T  [tf32, 64x64]
    cbgemm_kernel<<<dim3(4, 4, BB * NC), 256>>>();
    // 5. chunk states [tf32, __expf, double-buffered]
    states_kernel<<<BB * NC * NHEADS, 256>>>();
    // 6. inter-chunk scan [__expf]
    scan_kernel<<<(BB * NHEADS * HEADDIM * DSTATE + 255) / 256, 256>>>();
    // 7. Y [tf32, __expf, double-buffered]
    ydiag_kernel<<<BB * NC * NHEADS, 256>>>(Dp);
    // 8. gated RMS norm (vectorized)
    rms_kernel<<<NROWS, 256>>>(rms_w);
    // 9. out_proj
    gemm_tc<<<dim3(DMODEL / 128, NROWS / 128), 256, GT_SMEM>>>(
        p_y, W_out, b_out, p_hidden, NROWS, DMODEL, DINNER, 0);
    // 10. h = LN(hidden + x)  (vectorized)
    addln_kernel<<<NROWS, 256>>>(p_hidden, x, ln_g, ln_b, p_h);
    // 11. fc1 + hardswish
    gemm_tc<<<dim3(DFF / 128, NROWS / 128), 256, GT_SMEM>>>(
        p_h, fc1_w, fc1_b, p_ff, NROWS, DFF, DMODEL, 1);
    // 12. fc2
    gemm_tc<<<dim3(DMODEL / 128, NROWS / 128), 256, GT_SMEM>>>(
        p_ff, fc2_w, fc2_b, p_ff2, NROWS, DMODEL, DFF, 0);
    // 13. out = LN(ff2 + h)  (vectorized)
    addln_kernel<<<NROWS, 256>>>(p_ff2, p_h, ln2_g, ln2_b, out);
    // 14. time_diff passthrough
    cudaMemcpyAsync(out + (size_t)NROWS * DMODEL, time_diff,
                    (size_t)BB * SEQ * sizeof(float), cudaMemcpyDeviceToDevice);
}